// round 5
// baseline (speedup 1.0000x reference)
#include <cuda_runtime.h>
#include <cuda_bf16.h>
#include <cstddef>

// Problem constants
#define B_  4
#define C_  256
#define H_  64
#define W_  64
#define P_  (H_*W_)       // 4096
#define COMP_ 64
#define S2_ 4
#define K2_ 25
#define EPS_ 1e-5f
#define MPAD_ 28          // mask row padded to 28 floats

// Scratch (device globals; no allocation)
__device__ float g_act[B_ * COMP_ * P_];                    // 4.19 MB
__device__ float g_part[4][B_ * S2_ * P_ * MPAD_];          // partial logits, 4x7.34 MB
__device__ float g_mask2[B_ * S2_ * P_ * MPAD_];            // [b][s][p][28]  7.34 MB

// ---------------------------------------------------------------------------
// Kernel 1: 1x1 compression conv + BN(eval) + SiLU, split-K x2.
// grid (16 pxblk, 8 og, 4 b) = 512 blocks, block 512 (2 k-teams x 256 px).
// 262K threads (~86% occ).
// ---------------------------------------------------------------------------
__global__ __launch_bounds__(512) void k_compress(
    const float* __restrict__ x, const float* __restrict__ w_comp,
    const float* __restrict__ gamma, const float* __restrict__ beta,
    const float* __restrict__ mean, const float* __restrict__ var)
{
    __shared__ float ws[256][8];    // [c][o_local]
    __shared__ float red[256][8];   // partial sums from k-team 1

    const int og = blockIdx.y;
    const int b  = blockIdx.z;
    const int tid = threadIdx.x;
    const int half = tid >> 8;      // k-team
    const int t = tid & 255;        // pixel within block
    const int p = (blockIdx.x << 8) + t;

    for (int i = tid; i < 256 * 8; i += 512) {
        int o = i & 7, c = i >> 3;
        ws[c][o] = w_comp[(og * 8 + o) * 256 + c];
    }
    __syncthreads();

    float acc[8];
#pragma unroll
    for (int o = 0; o < 8; o++) acc[o] = 0.f;

    const float* xb = x + ((size_t)b * C_ + half * 128) * P_ + p;
    const int cbase = half * 128;
#pragma unroll 8
    for (int c = 0; c < 128; c++) {
        float xv = xb[(size_t)c * P_];
        float4 w0 = *(const float4*)&ws[cbase + c][0];
        float4 w1 = *(const float4*)&ws[cbase + c][4];
        acc[0] += w0.x * xv; acc[1] += w0.y * xv;
        acc[2] += w0.z * xv; acc[3] += w0.w * xv;
        acc[4] += w1.x * xv; acc[5] += w1.y * xv;
        acc[6] += w1.z * xv; acc[7] += w1.w * xv;
    }

    if (half == 1) {
#pragma unroll
        for (int o = 0; o < 8; o++) red[t][o] = acc[o];
    }
    __syncthreads();
    if (half == 0) {
#pragma unroll
        for (int o = 0; o < 8; o++) {
            int oc = og * 8 + o;
            float sc = gamma[oc] * rsqrtf(var[oc] + EPS_);
            float v = (acc[o] + red[t][o] - mean[oc]) * sc + beta[oc];
            float a = v / (1.f + __expf(-v));          // SiLU
            g_act[((size_t)b * COMP_ + oc) * P_ + p] = a;
        }
    }
}

// ---------------------------------------------------------------------------
// Kernel 2: 3x3 encoder conv, ci-split x4 -> partial logits.
// grid (16 tiles, s*4+quarter = 16, 4 b) = 1024 blocks, block 256 (16x16 px).
// smem 37KB static -> ~6 blocks/SM, ~75% occ.
// w layout transposed: w_s[q][cl][k] (k padded 25->28, float4 rows).
// ---------------------------------------------------------------------------
#define ENC_ACT_F (16 * 18 * 18)   // 5184
#define ENC_W_F   (9 * 16 * 28)    // 4032

__global__ __launch_bounds__(256) void k_encoder(const float* __restrict__ w_enc)
{
    __shared__ float act_s[ENC_ACT_F];   // [cl][yy][xx] pitch 18, 16 ch
    __shared__ float w_s[ENC_W_F];       // [q][cl][28]

    const int s = blockIdx.y >> 2;
    const int quarter = blockIdx.y & 3;
    const int b = blockIdx.z;
    const int tile = blockIdx.x;
    const int ty0 = (tile >> 2) * 16, tx0 = (tile & 3) * 16;
    const int tid = threadIdx.x;
    const int ci0 = quarter * 16;

    // w_s[q*448 + cl*28 + k] = w_enc[(k*4+s)*576 + (ci0+cl)*9 + q]
    for (int i = tid; i < 9 * 16 * 25; i += 256) {
        int q = i / 400, rem = i % 400;
        int cl = rem / 25, k = rem % 25;
        w_s[q * 448 + cl * 28 + k] = w_enc[(k * 4 + s) * 576 + (ci0 + cl) * 9 + q];
    }
    // act tile, pad=1, zero-fill
    for (int i = tid; i < ENC_ACT_F; i += 256) {
        int cl = i / 324, r = i % 324;
        int yy = r / 18, xx = r % 18;
        int gy = ty0 + yy - 1, gx = tx0 + xx - 1;
        float v = 0.f;
        if ((unsigned)gy < 64u && (unsigned)gx < 64u)
            v = g_act[((size_t)b * COMP_ + ci0 + cl) * P_ + gy * 64 + gx];
        act_s[i] = v;
    }
    __syncthreads();

    const int py = tid >> 4, px = tid & 15;
    float acc[25];
#pragma unroll
    for (int k = 0; k < 25; k++) acc[k] = 0.f;

    for (int cl = 0; cl < 16; cl++) {
        float a[9];
        const float* ap = act_s + cl * 324 + py * 18 + px;
#pragma unroll
        for (int dy = 0; dy < 3; dy++)
#pragma unroll
            for (int dx = 0; dx < 3; dx++)
                a[dy * 3 + dx] = ap[dy * 18 + dx];

#pragma unroll
        for (int q = 0; q < 9; q++) {
            const float4* wq = (const float4*)(w_s + q * 448 + cl * 28);
            float aq = a[q];
            float4 w0 = wq[0], w1 = wq[1], w2 = wq[2];
            float4 w3 = wq[3], w4 = wq[4], w5 = wq[5];
            float  w6 = ((const float*)(wq + 6))[0];
            acc[0]  += w0.x * aq; acc[1]  += w0.y * aq; acc[2]  += w0.z * aq; acc[3]  += w0.w * aq;
            acc[4]  += w1.x * aq; acc[5]  += w1.y * aq; acc[6]  += w1.z * aq; acc[7]  += w1.w * aq;
            acc[8]  += w2.x * aq; acc[9]  += w2.y * aq; acc[10] += w2.z * aq; acc[11] += w2.w * aq;
            acc[12] += w3.x * aq; acc[13] += w3.y * aq; acc[14] += w3.z * aq; acc[15] += w3.w * aq;
            acc[16] += w4.x * aq; acc[17] += w4.y * aq; acc[18] += w4.z * aq; acc[19] += w4.w * aq;
            acc[20] += w5.x * aq; acc[21] += w5.y * aq; acc[22] += w5.z * aq; acc[23] += w5.w * aq;
            acc[24] += w6   * aq;
        }
    }

    // store partial logits [quarter][b][s][p][28]
    const int gp = (ty0 + py) * 64 + tx0 + px;
    float4* mp = (float4*)(g_part[quarter] + (((size_t)b * S2_ + s) * P_ + gp) * MPAD_);
    mp[0] = make_float4(acc[0],  acc[1],  acc[2],  acc[3]);
    mp[1] = make_float4(acc[4],  acc[5],  acc[6],  acc[7]);
    mp[2] = make_float4(acc[8],  acc[9],  acc[10], acc[11]);
    mp[3] = make_float4(acc[12], acc[13], acc[14], acc[15]);
    mp[4] = make_float4(acc[16], acc[17], acc[18], acc[19]);
    mp[5] = make_float4(acc[20], acc[21], acc[22], acc[23]);
    mp[6] = make_float4(acc[24], 0.f, 0.f, 0.f);
}

// ---------------------------------------------------------------------------
// Kernel 2.5: combine 4 partials + softmax(25) -> g_mask2.
// grid 256, block 256; block covers 256 rows. Coalesced float4 via smem.
// ---------------------------------------------------------------------------
__global__ __launch_bounds__(256) void k_combine()
{
    __shared__ float sm[256 * MPAD_];
    const int tid = threadIdx.x;
    const size_t base = (size_t)blockIdx.x * 256 * MPAD_;   // float offset

    const float4* p0 = (const float4*)(g_part[0] + base);
    const float4* p1 = (const float4*)(g_part[1] + base);
    const float4* p2 = (const float4*)(g_part[2] + base);
    const float4* p3 = (const float4*)(g_part[3] + base);
    float4* smv = (float4*)sm;
#pragma unroll
    for (int j = 0; j < 7; j++) {
        int i = j * 256 + tid;
        float4 a = p0[i], b = p1[i], c = p2[i], d = p3[i];
        smv[i] = make_float4(a.x + b.x + c.x + d.x, a.y + b.y + c.y + d.y,
                             a.z + b.z + c.z + d.z, a.w + b.w + c.w + d.w);
    }
    __syncthreads();

    float v[25];
#pragma unroll
    for (int k = 0; k < 25; k++) v[k] = sm[tid * MPAD_ + k];
    float m = v[0];
#pragma unroll
    for (int k = 1; k < 25; k++) m = fmaxf(m, v[k]);
    float sum = 0.f;
#pragma unroll
    for (int k = 0; k < 25; k++) { v[k] = __expf(v[k] - m); sum += v[k]; }
    float inv = 1.f / sum;

    float4* mp = (float4*)(g_mask2 + base + (size_t)tid * MPAD_);
    mp[0] = make_float4(v[0]*inv,  v[1]*inv,  v[2]*inv,  v[3]*inv);
    mp[1] = make_float4(v[4]*inv,  v[5]*inv,  v[6]*inv,  v[7]*inv);
    mp[2] = make_float4(v[8]*inv,  v[9]*inv,  v[10]*inv, v[11]*inv);
    mp[3] = make_float4(v[12]*inv, v[13]*inv, v[14]*inv, v[15]*inv);
    mp[4] = make_float4(v[16]*inv, v[17]*inv, v[18]*inv, v[19]*inv);
    mp[5] = make_float4(v[20]*inv, v[21]*inv, v[22]*inv, v[23]*inv);
    mp[6] = make_float4(v[24]*inv, 0.f, 0.f, 0.f);
}

// ---------------------------------------------------------------------------
// Kernel 3: content-aware reassembly + pixel shuffle (R4 structure).
// grid (64 tiles of 8x8, 8 cgroups of 32, 4 b), block 256 = 64px*2csub*2sgrp.
// ---------------------------------------------------------------------------
__global__ __launch_bounds__(256, 2) void k_reassemble(
    const float* __restrict__ x, float* __restrict__ out)
{
    __shared__ float xs[32][144];        // [c_local][12x12]
    __shared__ float ms[256][MPAD_];     // [(s*64+px)][k]

    const int b = blockIdx.z;
    const int cg = blockIdx.y;
    const int tile = blockIdx.x;
    const int ty0 = (tile >> 3) * 8, tx0 = (tile & 7) * 8;
    const int tid = threadIdx.x;

    for (int i = tid; i < 32 * 144; i += 256) {
        int cl = i / 144, r = i % 144;
        int yy = r / 12, xx = r % 12;
        int gy = ty0 + yy - 2, gx = tx0 + xx - 2;
        float v = 0.f;
        if ((unsigned)gy < 64u && (unsigned)gx < 64u)
            v = x[(((size_t)b * C_ + cg * 32 + cl) * 64 + gy) * 64 + gx];
        xs[cl][r] = v;
    }
    for (int i = tid; i < 256 * 7; i += 256) {
        int row = i / 7, j = i % 7;
        int s = row >> 6, px = row & 63;
        int gp = (ty0 + (px >> 3)) * 64 + tx0 + (px & 7);
        const float4* src = (const float4*)(g_mask2 + (((size_t)b * S2_ + s) * P_ + gp) * MPAD_);
        *((float4*)ms[row] + j) = src[j];
    }
    __syncthreads();

    const int sgrp = tid >> 7;
    const int csub = (tid >> 6) & 1;
    const int px   = tid & 63;
    const int py = px >> 3, pxl = px & 7;

    float mk0[25], mk1[25];
#pragma unroll
    for (int k = 0; k < 25; k++) {
        mk0[k] = ms[(sgrp * 2 + 0) * 64 + px][k];
        mk1[k] = ms[(sgrp * 2 + 1) * 64 + px][k];
    }

    const int gy = ty0 + py, gx = tx0 + pxl;
    const size_t row_base = (((size_t)b * C_ + cg * 32) * 128 + 2 * gy + sgrp) * 128 + 2 * gx;

#pragma unroll
    for (int cc = 0; cc < 16; cc++) {
        int cl = csub * 16 + cc;
        float xr[25];
#pragma unroll
        for (int dy = 0; dy < 5; dy++)
#pragma unroll
            for (int dx = 0; dx < 5; dx++)
                xr[dy * 5 + dx] = xs[cl][(py + dy) * 12 + pxl + dx];

        float a0 = 0.f, a1 = 0.f;
#pragma unroll
        for (int k = 0; k < 25; k++) {
            a0 += mk0[k] * xr[k];
            a1 += mk1[k] * xr[k];
        }
        *(float2*)(out + row_base + (size_t)cl * 128 * 128) = make_float2(a0, a1);
    }
}

// ---------------------------------------------------------------------------
extern "C" void kernel_launch(void* const* d_in, const int* in_sizes, int n_in,
                              void* d_out, int out_size)
{
    const float* x       = (const float*)d_in[0];
    const float* w_comp  = (const float*)d_in[1];
    const float* bn_g    = (const float*)d_in[2];
    const float* bn_b    = (const float*)d_in[3];
    const float* bn_m    = (const float*)d_in[4];
    const float* bn_v    = (const float*)d_in[5];
    const float* w_enc   = (const float*)d_in[6];
    float* out = (float*)d_out;

    dim3 g1(16, 8, B_);
    k_compress<<<g1, 512>>>(x, w_comp, bn_g, bn_b, bn_m, bn_v);

    dim3 g2(16, 16, B_);
    k_encoder<<<g2, 256>>>(w_enc);

    k_combine<<<256, 256>>>();

    dim3 g3(64, 8, B_);
    k_reassemble<<<g3, 256>>>(x, out);
}

// round 6
// speedup vs baseline: 1.6193x; 1.6193x over previous
#include <cuda_runtime.h>
#include <cuda_bf16.h>
#include <cstddef>

// Problem constants
#define B_  4
#define C_  256
#define H_  64
#define W_  64
#define P_  (H_*W_)       // 4096
#define COMP_ 64
#define S2_ 4
#define K2_ 25
#define EPS_ 1e-5f
#define MPAD_ 28          // mask gmem row padded to 28 floats (16B aligned)

// Scratch (device globals; no allocation)
__device__ float g_act[B_ * COMP_ * P_];                 // 4.19 MB
__device__ float g_mask2[B_ * S2_ * P_ * MPAD_];         // [b][s][p][28]  7.34 MB

// ---------------------------------------------------------------------------
// Kernel 1: 1x1 compression conv + BatchNorm(eval) + SiLU   (R3 exact, 38.7us)
// grid (16 pxblocks, 8 outgroups, 4 b), block 256. Thread: 1 pixel x 8 outputs.
// ---------------------------------------------------------------------------
__global__ __launch_bounds__(256) void k_compress(
    const float* __restrict__ x, const float* __restrict__ w_comp,
    const float* __restrict__ gamma, const float* __restrict__ beta,
    const float* __restrict__ mean, const float* __restrict__ var)
{
    __shared__ float ws[256][8];    // [c][o_local]
    const int og = blockIdx.y;
    const int b  = blockIdx.z;
    const int p  = (blockIdx.x << 8) + threadIdx.x;

    for (int i = threadIdx.x; i < 256 * 8; i += 256) {
        int o = i & 7, c = i >> 3;
        ws[c][o] = w_comp[(og * 8 + o) * 256 + c];
    }
    __syncthreads();

    float acc[8];
#pragma unroll
    for (int o = 0; o < 8; o++) acc[o] = 0.f;

    const float* xb = x + ((size_t)b * C_) * P_ + p;
#pragma unroll 8
    for (int c = 0; c < 256; c++) {
        float xv = xb[(size_t)c * P_];
        float4 w0 = *(const float4*)&ws[c][0];
        float4 w1 = *(const float4*)&ws[c][4];
        acc[0] += w0.x * xv; acc[1] += w0.y * xv;
        acc[2] += w0.z * xv; acc[3] += w0.w * xv;
        acc[4] += w1.x * xv; acc[5] += w1.y * xv;
        acc[6] += w1.z * xv; acc[7] += w1.w * xv;
    }

#pragma unroll
    for (int o = 0; o < 8; o++) {
        int oc = og * 8 + o;
        float sc = gamma[oc] * rsqrtf(var[oc] + EPS_);
        float v = (acc[o] - mean[oc]) * sc + beta[oc];
        float a = v / (1.f + __expf(-v));          // SiLU
        g_act[((size_t)b * COMP_ + oc) * P_ + p] = a;
    }
}

// ---------------------------------------------------------------------------
// Kernel 2: 3x3 encoder conv (64->25 per s-slice) + softmax(25)  (R3 exact)
// grid (16 tiles, 4 s, 4 b), block 256 (16x16 px). Two ci passes (32+32).
// ---------------------------------------------------------------------------
#define ENC_ACT_FLOATS (32 * 18 * 18)        // 10368
#define ENC_W_FLOATS   (25 * 32 * 12)        // 9600 (rows padded 9->12)
#define ENC_SMEM_BYTES ((ENC_ACT_FLOATS + ENC_W_FLOATS) * 4)   // 79872

__global__ __launch_bounds__(256) void k_encoder(const float* __restrict__ w_enc)
{
    extern __shared__ float sm[];
    float* act_s = sm;                      // [cl][yy][xx] pitch 18 (32 ch)
    float* w_s   = sm + ENC_ACT_FLOATS;     // [k][cl][12]

    const int s = blockIdx.y;
    const int b = blockIdx.z;
    const int tile = blockIdx.x;
    const int ty0 = (tile >> 2) * 16, tx0 = (tile & 3) * 16;
    const int tid = threadIdx.x;
    const int py = tid >> 4, px = tid & 15;

    float acc[25];
#pragma unroll
    for (int k = 0; k < 25; k++) acc[k] = 0.f;

    for (int pass = 0; pass < 2; pass++) {
        if (pass) __syncthreads();
        const int ci0 = pass * 32;

        for (int i = tid; i < 25 * 288; i += 256) {
            int k = i / 288, rem = i % 288;
            int cl = rem / 9, q = rem % 9;
            w_s[k * 384 + cl * 12 + q] = w_enc[(k * 4 + s) * 576 + (ci0 + cl) * 9 + q];
        }
        for (int i = tid; i < ENC_ACT_FLOATS; i += 256) {
            int cl = i / 324, r = i % 324;
            int yy = r / 18, xx = r % 18;
            int gy = ty0 + yy - 1, gx = tx0 + xx - 1;
            float v = 0.f;
            if ((unsigned)gy < 64u && (unsigned)gx < 64u)
                v = g_act[((size_t)b * COMP_ + ci0 + cl) * P_ + gy * 64 + gx];
            act_s[i] = v;
        }
        __syncthreads();

        for (int cl = 0; cl < 32; cl++) {
            float a[9];
            const float* ap = act_s + cl * 324 + py * 18 + px;
#pragma unroll
            for (int dy = 0; dy < 3; dy++)
#pragma unroll
                for (int dx = 0; dx < 3; dx++)
                    a[dy * 3 + dx] = ap[dy * 18 + dx];

            const float4* wbase = (const float4*)(w_s + cl * 12);
#pragma unroll
            for (int k = 0; k < 25; k++) {
                const float4* wk = wbase + k * 96;
                float4 w0 = wk[0], w1 = wk[1], w2 = wk[2];
                acc[k] += w0.x * a[0] + w0.y * a[1] + w0.z * a[2] +
                          w0.w * a[3] + w1.x * a[4] + w1.y * a[5] +
                          w1.z * a[6] + w1.w * a[7] + w2.x * a[8];
            }
        }
    }

    float m = acc[0];
#pragma unroll
    for (int k = 1; k < 25; k++) m = fmaxf(m, acc[k]);
    float sum = 0.f;
#pragma unroll
    for (int k = 0; k < 25; k++) { acc[k] = __expf(acc[k] - m); sum += acc[k]; }
    float inv = 1.f / sum;
#pragma unroll
    for (int k = 0; k < 25; k++) acc[k] *= inv;

    const int gp = (ty0 + py) * 64 + tx0 + px;
    float4* mp = (float4*)(g_mask2 + (((size_t)b * S2_ + s) * P_ + gp) * MPAD_);
    mp[0] = make_float4(acc[0],  acc[1],  acc[2],  acc[3]);
    mp[1] = make_float4(acc[4],  acc[5],  acc[6],  acc[7]);
    mp[2] = make_float4(acc[8],  acc[9],  acc[10], acc[11]);
    mp[3] = make_float4(acc[12], acc[13], acc[14], acc[15]);
    mp[4] = make_float4(acc[16], acc[17], acc[18], acc[19]);
    mp[5] = make_float4(acc[20], acc[21], acc[22], acc[23]);
    mp[6] = make_float4(acc[24], 0.f, 0.f, 0.f);
}

// ---------------------------------------------------------------------------
// Kernel 3: reassembly + pixel shuffle — 4-s reuse, k-chunked, conflict-free.
// grid (64 tiles of 8x8, 16 cgroups of 16, 4 b) = 4096 blocks.
// block 256 = 64 px * 4 csub (4 channels each); each thread computes all 4 s.
// smem: xs [16ch][12 rows pitch 40]  (40*py mod 32 = 8*py -> 0 conflicts)
//       ms [256 rows][29]            (odd stride  -> 0 conflicts)
// ---------------------------------------------------------------------------
#define RA_XS_F  (16 * 480)                  // 7680 floats
#define RA_MS_F  (256 * 29)                  // 7424 floats
#define RA_SMEM_BYTES ((RA_XS_F + RA_MS_F) * 4)   // 60416 B

__global__ __launch_bounds__(256, 3) void k_reassemble(
    const float* __restrict__ x, float* __restrict__ out)
{
    extern __shared__ float rsm[];
    float* xs = rsm;                 // [cl][yy*40 + xx]
    float* ms = rsm + RA_XS_F;       // [(s*64+px)*29 + k]

    const int b = blockIdx.z;
    const int cg = blockIdx.y;       // 16 channel groups of 16
    const int tile = blockIdx.x;
    const int ty0 = (tile >> 3) * 8, tx0 = (tile & 7) * 8;
    const int tid = threadIdx.x;

    // x tile (halo 2, zero pad), pitched rows
    for (int i = tid; i < 16 * 144; i += 256) {
        int cl = i / 144, r = i % 144;
        int yy = r / 12, xx = r % 12;
        int gy = ty0 + yy - 2, gx = tx0 + xx - 2;
        float v = 0.f;
        if ((unsigned)gy < 64u && (unsigned)gx < 64u)
            v = x[(((size_t)b * C_ + cg * 16 + cl) * 64 + gy) * 64 + gx];
        xs[cl * 480 + yy * 40 + xx] = v;
    }
    // mask tile: float4 gmem reads -> scalar stores into 29-pitch rows
    for (int i = tid; i < 256 * 7; i += 256) {
        int row = i / 7, j = i % 7;
        int s = row >> 6, px = row & 63;
        int gp = (ty0 + (px >> 3)) * 64 + tx0 + (px & 7);
        float4 v = *((const float4*)(g_mask2 +
                     (((size_t)b * S2_ + s) * P_ + gp) * MPAD_) + j);
        float* dst = ms + row * 29 + j * 4;
        dst[0] = v.x; dst[1] = v.y; dst[2] = v.z; dst[3] = v.w;
    }
    __syncthreads();

    const int csub = tid >> 6;           // 4 channels each
    const int px   = tid & 63;
    const int py = px >> 3, pxl = px & 7;

    float acc[4][4];                     // [ch][s]
#pragma unroll
    for (int ch = 0; ch < 4; ch++)
#pragma unroll
        for (int s = 0; s < 4; s++) acc[ch][s] = 0.f;

    const float* xbase = xs + csub * 4 * 480 + py * 40 + pxl;
    const float* mbase = ms + px * 29;

    // chunks over dy rows: {0,1}(k 0..9), {2,3}(k 10..19), {4}(k 20..24)
#pragma unroll
    for (int chunk = 0; chunk < 3; chunk++) {
        const int dy0 = chunk * 2;
        const int nk  = (chunk == 2) ? 5 : 10;
        const int kb  = dy0 * 5;

        float mk[4][10];
#pragma unroll
        for (int s = 0; s < 4; s++)
#pragma unroll
            for (int j = 0; j < 10; j++)
                if (j < nk) mk[s][j] = mbase[s * 64 * 29 + kb + j];

#pragma unroll
        for (int ch = 0; ch < 4; ch++) {
            const float* xp = xbase + ch * 480 + dy0 * 40;
            float xr[10];
#pragma unroll
            for (int j = 0; j < 10; j++)
                if (j < nk) xr[j] = xp[(j / 5) * 40 + (j % 5)];

#pragma unroll
            for (int j = 0; j < 10; j++) {
                if (j < nk) {
                    acc[ch][0] += mk[0][j] * xr[j];
                    acc[ch][1] += mk[1][j] * xr[j];
                    acc[ch][2] += mk[2][j] * xr[j];
                    acc[ch][3] += mk[3][j] * xr[j];
                }
            }
        }
    }

    const int gy = ty0 + py, gx = tx0 + pxl;
    size_t base = (((size_t)b * C_ + cg * 16 + csub * 4) * 128 + 2 * gy) * 128 + 2 * gx;
#pragma unroll
    for (int ch = 0; ch < 4; ch++) {
        *(float2*)(out + base)       = make_float2(acc[ch][0], acc[ch][1]);
        *(float2*)(out + base + 128) = make_float2(acc[ch][2], acc[ch][3]);
        base += (size_t)128 * 128;
    }
}

// ---------------------------------------------------------------------------
extern "C" void kernel_launch(void* const* d_in, const int* in_sizes, int n_in,
                              void* d_out, int out_size)
{
    const float* x       = (const float*)d_in[0];
    const float* w_comp  = (const float*)d_in[1];
    const float* bn_g    = (const float*)d_in[2];
    const float* bn_b    = (const float*)d_in[3];
    const float* bn_m    = (const float*)d_in[4];
    const float* bn_v    = (const float*)d_in[5];
    const float* w_enc   = (const float*)d_in[6];
    float* out = (float*)d_out;

    cudaFuncSetAttribute(k_encoder, cudaFuncAttributeMaxDynamicSharedMemorySize,
                         ENC_SMEM_BYTES);
    cudaFuncSetAttribute(k_reassemble, cudaFuncAttributeMaxDynamicSharedMemorySize,
                         RA_SMEM_BYTES);

    dim3 g1(16, 8, B_);
    k_compress<<<g1, 256>>>(x, w_comp, bn_g, bn_b, bn_m, bn_v);

    dim3 g2(16, 4, B_);
    k_encoder<<<g2, 256, ENC_SMEM_BYTES>>>(w_enc);

    dim3 g3(64, 16, B_);
    k_reassemble<<<g3, 256, RA_SMEM_BYTES>>>(x, out);
}

// round 7
// speedup vs baseline: 1.7173x; 1.0605x over previous
#include <cuda_runtime.h>
#include <cuda_bf16.h>
#include <cstddef>

// Problem constants
#define B_  4
#define C_  256
#define H_  64
#define W_  64
#define P_  (H_*W_)       // 4096
#define COMP_ 64
#define S2_ 4
#define K2_ 25
#define EPS_ 1e-5f
#define MPAD_ 28          // mask gmem row padded to 28 floats (16B aligned)

typedef unsigned long long ull;

// ---- packed fp32x2 helpers (Blackwell FFMA2; IEEE fp32 per lane) ----------
__device__ __forceinline__ ull pk2(float lo, float hi) {
    ull r; asm("mov.b64 %0, {%1, %2};" : "=l"(r) : "f"(lo), "f"(hi)); return r;
}
__device__ __forceinline__ void upk2(ull v, float& lo, float& hi) {
    asm("mov.b64 {%0, %1}, %2;" : "=f"(lo), "=f"(hi) : "l"(v));
}
__device__ __forceinline__ ull fma2(ull a, ull b, ull c) {
    ull d; asm("fma.rn.f32x2 %0, %1, %2, %3;" : "=l"(d) : "l"(a), "l"(b), "l"(c));
    return d;
}

// Scratch (device globals; no allocation)
__device__ float g_act[B_ * COMP_ * P_];                 // 4.19 MB
__device__ float g_mask2[B_ * S2_ * P_ * MPAD_];         // [b][s][p][28]  7.34 MB

// ---------------------------------------------------------------------------
// Kernel 1: 1x1 compression conv + BN(eval) + SiLU.  (R3 structure + FFMA2)
// grid (16 pxblocks, 8 outgroups, 4 b), block 256. Thread: 1 px x 8 outputs.
// ---------------------------------------------------------------------------
__global__ __launch_bounds__(256) void k_compress(
    const float* __restrict__ x, const float* __restrict__ w_comp,
    const float* __restrict__ gamma, const float* __restrict__ beta,
    const float* __restrict__ mean, const float* __restrict__ var)
{
    __shared__ float ws[256][8];    // [c][o_local]
    const int og = blockIdx.y;
    const int b  = blockIdx.z;
    const int p  = (blockIdx.x << 8) + threadIdx.x;

    for (int i = threadIdx.x; i < 256 * 8; i += 256) {
        int o = i & 7, c = i >> 3;
        ws[c][o] = w_comp[(og * 8 + o) * 256 + c];
    }
    __syncthreads();

    ull acc2[4];
#pragma unroll
    for (int j = 0; j < 4; j++) acc2[j] = 0ull;

    const float* xb = x + ((size_t)b * C_) * P_ + p;
#pragma unroll 8
    for (int c = 0; c < 256; c++) {
        float xv = xb[(size_t)c * P_];
        ull xx = pk2(xv, xv);
        ulonglong2 wA = *(const ulonglong2*)&ws[c][0];
        ulonglong2 wB = *(const ulonglong2*)&ws[c][4];
        acc2[0] = fma2(wA.x, xx, acc2[0]);
        acc2[1] = fma2(wA.y, xx, acc2[1]);
        acc2[2] = fma2(wB.x, xx, acc2[2]);
        acc2[3] = fma2(wB.y, xx, acc2[3]);
    }

    float acc[8];
#pragma unroll
    for (int j = 0; j < 4; j++) upk2(acc2[j], acc[2 * j], acc[2 * j + 1]);

#pragma unroll
    for (int o = 0; o < 8; o++) {
        int oc = og * 8 + o;
        float sc = gamma[oc] * rsqrtf(var[oc] + EPS_);
        float v = (acc[o] - mean[oc]) * sc + beta[oc];
        float a = v / (1.f + __expf(-v));          // SiLU
        g_act[((size_t)b * COMP_ + oc) * P_ + p] = a;
    }
}

// ---------------------------------------------------------------------------
// Kernel 2: 3x3 encoder conv (64->25 per s-slice) + softmax(25), FFMA2 k-pairs.
// grid (16 tiles, 4 s, 4 b), block 256 (16x16 px). Two ci passes (32+32).
// w layout [cl][q][28] (k contiguous, k>=25 zeroed).
// ---------------------------------------------------------------------------
#define ENC_ACT_FLOATS (32 * 18 * 18)        // 10368
#define ENC_W_FLOATS   (32 * 9 * 28)         // 8064
#define ENC_SMEM_BYTES ((ENC_ACT_FLOATS + ENC_W_FLOATS) * 4)   // 73728

__global__ __launch_bounds__(256) void k_encoder(const float* __restrict__ w_enc)
{
    extern __shared__ float sm[];
    float* act_s = sm;                      // [cl][yy][xx] pitch 18 (32 ch)
    float* w_s   = sm + ENC_ACT_FLOATS;     // [cl][q][28]

    const int s = blockIdx.y;
    const int b = blockIdx.z;
    const int tile = blockIdx.x;
    const int ty0 = (tile >> 2) * 16, tx0 = (tile & 3) * 16;
    const int tid = threadIdx.x;
    const int py = tid >> 4, px = tid & 15;

    ull acc2[13];
#pragma unroll
    for (int k = 0; k < 13; k++) acc2[k] = 0ull;

    for (int pass = 0; pass < 2; pass++) {
        if (pass) __syncthreads();
        const int ci0 = pass * 32;

        // w_s[(cl*9+q)*28 + k], zero for k>=25
        for (int i = tid; i < ENC_W_FLOATS; i += 256) {
            int k = i % 28, cq = i / 28;
            int cl = cq / 9, q = cq % 9;
            float v = 0.f;
            if (k < 25) v = w_enc[(k * 4 + s) * 576 + (ci0 + cl) * 9 + q];
            w_s[i] = v;
        }
        for (int i = tid; i < ENC_ACT_FLOATS; i += 256) {
            int cl = i / 324, r = i % 324;
            int yy = r / 18, xx = r % 18;
            int gy = ty0 + yy - 1, gx = tx0 + xx - 1;
            float v = 0.f;
            if ((unsigned)gy < 64u && (unsigned)gx < 64u)
                v = g_act[((size_t)b * COMP_ + ci0 + cl) * P_ + gy * 64 + gx];
            act_s[i] = v;
        }
        __syncthreads();

        for (int cl = 0; cl < 32; cl++) {
            float a[9];
            const float* ap = act_s + cl * 324 + py * 18 + px;
#pragma unroll
            for (int dy = 0; dy < 3; dy++)
#pragma unroll
                for (int dx = 0; dx < 3; dx++)
                    a[dy * 3 + dx] = ap[dy * 18 + dx];

#pragma unroll
            for (int q = 0; q < 9; q++) {
                const ulonglong2* wq = (const ulonglong2*)(w_s + (cl * 9 + q) * 28);
                ull aa = pk2(a[q], a[q]);
                ulonglong2 w0 = wq[0], w1 = wq[1], w2 = wq[2];
                ulonglong2 w3 = wq[3], w4 = wq[4], w5 = wq[5];
                ull w6 = ((const ull*)(wq + 6))[0];
                acc2[0]  = fma2(w0.x, aa, acc2[0]);
                acc2[1]  = fma2(w0.y, aa, acc2[1]);
                acc2[2]  = fma2(w1.x, aa, acc2[2]);
                acc2[3]  = fma2(w1.y, aa, acc2[3]);
                acc2[4]  = fma2(w2.x, aa, acc2[4]);
                acc2[5]  = fma2(w2.y, aa, acc2[5]);
                acc2[6]  = fma2(w3.x, aa, acc2[6]);
                acc2[7]  = fma2(w3.y, aa, acc2[7]);
                acc2[8]  = fma2(w4.x, aa, acc2[8]);
                acc2[9]  = fma2(w4.y, aa, acc2[9]);
                acc2[10] = fma2(w5.x, aa, acc2[10]);
                acc2[11] = fma2(w5.y, aa, acc2[11]);
                acc2[12] = fma2(w6,   aa, acc2[12]);
            }
        }
    }

    float acc[26];
#pragma unroll
    for (int k = 0; k < 13; k++) upk2(acc2[k], acc[2 * k], acc[2 * k + 1]);

    float m = acc[0];
#pragma unroll
    for (int k = 1; k < 25; k++) m = fmaxf(m, acc[k]);
    float sum = 0.f;
#pragma unroll
    for (int k = 0; k < 25; k++) { acc[k] = __expf(acc[k] - m); sum += acc[k]; }
    float inv = 1.f / sum;
#pragma unroll
    for (int k = 0; k < 25; k++) acc[k] *= inv;

    const int gp = (ty0 + py) * 64 + tx0 + px;
    float4* mp = (float4*)(g_mask2 + (((size_t)b * S2_ + s) * P_ + gp) * MPAD_);
    mp[0] = make_float4(acc[0],  acc[1],  acc[2],  acc[3]);
    mp[1] = make_float4(acc[4],  acc[5],  acc[6],  acc[7]);
    mp[2] = make_float4(acc[8],  acc[9],  acc[10], acc[11]);
    mp[3] = make_float4(acc[12], acc[13], acc[14], acc[15]);
    mp[4] = make_float4(acc[16], acc[17], acc[18], acc[19]);
    mp[5] = make_float4(acc[20], acc[21], acc[22], acc[23]);
    mp[6] = make_float4(acc[24], 0.f, 0.f, 0.f);
}

// ---------------------------------------------------------------------------
// Kernel 3: reassembly + pixel shuffle, FFMA2 s-pairs.
// grid (64 tiles of 8x8, 16 cgroups of 16, 4 b), block 256 = 64px * 4csub(4ch).
// smem: xs [16ch][12 rows pitch 40] (conflict-free)
//       ms [64px][25k][4s] pitch 108 (LDS.128 -> 2 f32x2 operands, conflict-free)
// ---------------------------------------------------------------------------
#define RA_XS_F  (16 * 480)                  // 7680
#define RA_MS_F  (64 * 108)                  // 6912
#define RA_SMEM_BYTES ((RA_XS_F + RA_MS_F) * 4)   // 58368

__global__ __launch_bounds__(256, 3) void k_reassemble(
    const float* __restrict__ x, float* __restrict__ out)
{
    extern __shared__ float rsm[];
    float* xs = rsm;                 // [cl][yy*40 + xx]
    float* ms = rsm + RA_XS_F;       // [px*108 + k*4 + s]

    const int b = blockIdx.z;
    const int cg = blockIdx.y;       // 16 channel groups of 16
    const int tile = blockIdx.x;
    const int ty0 = (tile >> 3) * 8, tx0 = (tile & 7) * 8;
    const int tid = threadIdx.x;

    // x tile (halo 2, zero pad), pitched rows
    for (int i = tid; i < 16 * 144; i += 256) {
        int cl = i / 144, r = i % 144;
        int yy = r / 12, xx = r % 12;
        int gy = ty0 + yy - 2, gx = tx0 + xx - 2;
        float v = 0.f;
        if ((unsigned)gy < 64u && (unsigned)gx < 64u)
            v = x[(((size_t)b * C_ + cg * 16 + cl) * 64 + gy) * 64 + gx];
        xs[cl * 480 + yy * 40 + xx] = v;
    }
    // mask tile: transpose to [px][k][s] while loading (float4 gmem reads)
    for (int i = tid; i < 64 * 4 * 7; i += 256) {
        int px = i / 28, rem = i % 28;
        int s = rem / 7, j = rem % 7;
        int gp = (ty0 + (px >> 3)) * 64 + tx0 + (px & 7);
        float4 v = *((const float4*)(g_mask2 +
                     (((size_t)b * S2_ + s) * P_ + gp) * MPAD_) + j);
        float* dst = ms + px * 108 + s;
        int k = j * 4;
        dst[(k + 0) * 4] = v.x;
        if (k + 1 < 25) dst[(k + 1) * 4] = v.y;
        if (k + 2 < 25) dst[(k + 2) * 4] = v.z;
        if (k + 3 < 25) dst[(k + 3) * 4] = v.w;
    }
    __syncthreads();

    const int csub = tid >> 6;           // 4 channels each
    const int px   = tid & 63;
    const int py = px >> 3, pxl = px & 7;

    ull acc01[4], acc23[4];
#pragma unroll
    for (int ch = 0; ch < 4; ch++) { acc01[ch] = 0ull; acc23[ch] = 0ull; }

    const float* xbase = xs + csub * 4 * 480 + py * 40 + pxl;
    const ulonglong2* mrow = (const ulonglong2*)(ms + px * 108);   // [k]

    // chunks of k: 10, 10, 5
#pragma unroll
    for (int chunk = 0; chunk < 3; chunk++) {
        const int kb = chunk * 10;
        const int nk = (chunk == 2) ? 5 : 10;

        ull mk01[10], mk23[10];
#pragma unroll
        for (int j = 0; j < 10; j++) {
            if (j < nk) {
                ulonglong2 m = mrow[kb + j];
                mk01[j] = m.x; mk23[j] = m.y;
            }
        }

#pragma unroll
        for (int ch = 0; ch < 4; ch++) {
            const float* xp = xbase + ch * 480;
#pragma unroll
            for (int j = 0; j < 10; j++) {
                if (j < nk) {
                    int k = kb + j;
                    float xv = xp[(k / 5) * 40 + (k % 5)];
                    ull xx = pk2(xv, xv);
                    acc01[ch] = fma2(mk01[j], xx, acc01[ch]);
                    acc23[ch] = fma2(mk23[j], xx, acc23[ch]);
                }
            }
        }
    }

    const int gy = ty0 + py, gx = tx0 + pxl;
    size_t base = (((size_t)b * C_ + cg * 16 + csub * 4) * 128 + 2 * gy) * 128 + 2 * gx;
#pragma unroll
    for (int ch = 0; ch < 4; ch++) {
        *(ull*)(out + base)       = acc01[ch];   // (s00, s01)
        *(ull*)(out + base + 128) = acc23[ch];   // (s10, s11)
        base += (size_t)128 * 128;
    }
}

// ---------------------------------------------------------------------------
extern "C" void kernel_launch(void* const* d_in, const int* in_sizes, int n_in,
                              void* d_out, int out_size)
{
    const float* x       = (const float*)d_in[0];
    const float* w_comp  = (const float*)d_in[1];
    const float* bn_g    = (const float*)d_in[2];
    const float* bn_b    = (const float*)d_in[3];
    const float* bn_m    = (const float*)d_in[4];
    const float* bn_v    = (const float*)d_in[5];
    const float* w_enc   = (const float*)d_in[6];
    float* out = (float*)d_out;

    cudaFuncSetAttribute(k_encoder, cudaFuncAttributeMaxDynamicSharedMemorySize,
                         ENC_SMEM_BYTES);
    cudaFuncSetAttribute(k_reassemble, cudaFuncAttributeMaxDynamicSharedMemorySize,
                         RA_SMEM_BYTES);

    dim3 g1(16, 8, B_);
    k_compress<<<g1, 256>>>(x, w_comp, bn_g, bn_b, bn_m, bn_v);

    dim3 g2(16, 4, B_);
    k_encoder<<<g2, 256, ENC_SMEM_BYTES>>>(w_enc);

    dim3 g3(64, 16, B_);
    k_reassemble<<<g3, 256, RA_SMEM_BYTES>>>(x, out);
}

// round 12
// speedup vs baseline: 1.7686x; 1.0299x over previous
#include <cuda_runtime.h>
#include <cuda_bf16.h>
#include <cstddef>

// Problem constants
#define B_  4
#define C_  256
#define H_  64
#define W_  64
#define P_  (H_*W_)       // 4096
#define COMP_ 64
#define S2_ 4
#define K2_ 25
#define EPS_ 1e-5f
#define MPAD_ 28          // mask gmem row padded to 28 floats (16B aligned)

typedef unsigned long long ull;

// ---- packed fp32x2 helpers (Blackwell FFMA2; IEEE fp32 per lane) ----------
__device__ __forceinline__ ull pk2(float lo, float hi) {
    ull r; asm("mov.b64 %0, {%1, %2};" : "=l"(r) : "f"(lo), "f"(hi)); return r;
}
__device__ __forceinline__ void upk2(ull v, float& lo, float& hi) {
    asm("mov.b64 {%0, %1}, %2;" : "=f"(lo), "=f"(hi) : "l"(v));
}
__device__ __forceinline__ ull fma2(ull a, ull b, ull c) {
    ull d; asm("fma.rn.f32x2 %0, %1, %2, %3;" : "=l"(d) : "l"(a), "l"(b), "l"(c));
    return d;
}
__device__ __forceinline__ ull add2(ull a, ull b) {
    ull d; asm("add.rn.f32x2 %0, %1, %2;" : "=l"(d) : "l"(a), "l"(b));
    return d;
}

// Scratch (device globals; no allocation)
__device__ float g_act[B_ * COMP_ * P_];                    // 4.19 MB
__device__ float g_part[4][B_ * S2_ * P_ * MPAD_];          // 4 x 7.34 MB partial logits
__device__ float g_mask2[B_ * S2_ * P_ * MPAD_];            // [b][s][p][28]  7.34 MB

// ---------------------------------------------------------------------------
// Kernel 1: 1x1 compression conv + BN(eval) + SiLU, split-K x2 + FFMA2.
// grid (16 pxblk, 8 og, 4 b) = 512 blocks, block 512 (2 c-teams x 256 px).
// 262K threads (~84% occ).
// ---------------------------------------------------------------------------
__global__ __launch_bounds__(512) void k_compress(
    const float* __restrict__ x, const float* __restrict__ w_comp,
    const float* __restrict__ gamma, const float* __restrict__ beta,
    const float* __restrict__ mean, const float* __restrict__ var)
{
    __shared__ float ws[256][8];    // [c][o_local]
    __shared__ ull   red[256][4];   // team-1 partial sums (packed pairs)

    const int og = blockIdx.y;
    const int b  = blockIdx.z;
    const int tid = threadIdx.x;
    const int half = tid >> 8;      // c-team
    const int t = tid & 255;        // pixel within block
    const int p = (blockIdx.x << 8) + t;

    for (int i = tid; i < 256 * 8; i += 512) {
        int o = i & 7, c = i >> 3;
        ws[c][o] = w_comp[(og * 8 + o) * 256 + c];
    }
    __syncthreads();

    ull acc2[4];
#pragma unroll
    for (int j = 0; j < 4; j++) acc2[j] = 0ull;

    const float* xb = x + ((size_t)b * C_ + half * 128) * P_ + p;
    const int cbase = half * 128;
#pragma unroll 8
    for (int c = 0; c < 128; c++) {
        float xv = xb[(size_t)c * P_];
        ull xx = pk2(xv, xv);
        ulonglong2 wA = *(const ulonglong2*)&ws[cbase + c][0];
        ulonglong2 wB = *(const ulonglong2*)&ws[cbase + c][4];
        acc2[0] = fma2(wA.x, xx, acc2[0]);
        acc2[1] = fma2(wA.y, xx, acc2[1]);
        acc2[2] = fma2(wB.x, xx, acc2[2]);
        acc2[3] = fma2(wB.y, xx, acc2[3]);
    }

    if (half == 1) {
#pragma unroll
        for (int j = 0; j < 4; j++) red[t][j] = acc2[j];
    }
    __syncthreads();
    if (half == 0) {
        float acc[8];
#pragma unroll
        for (int j = 0; j < 4; j++) {
            ull s = add2(acc2[j], red[t][j]);
            upk2(s, acc[2 * j], acc[2 * j + 1]);
        }
#pragma unroll
        for (int o = 0; o < 8; o++) {
            int oc = og * 8 + o;
            float sc = gamma[oc] * rsqrtf(var[oc] + EPS_);
            float v = (acc[o] - mean[oc]) * sc + beta[oc];
            float a = v / (1.f + __expf(-v));          // SiLU
            g_act[((size_t)b * COMP_ + oc) * P_ + p] = a;
        }
    }
}

// ---------------------------------------------------------------------------
// Kernel 2: 3x3 encoder conv, ci-split x4, FFMA2 k-pairs -> partial logits.
// grid (16 tiles, s*4+quarter = 16, 4 b) = 1024 blocks, block 256 (16x16 px).
// smem 36.9KB static -> 6 blocks/SM, ~75% occ.
// w layout [cl][q][28] (k contiguous, k>=25 zeroed), FFMA2 over k-pairs.
// ---------------------------------------------------------------------------
#define ENC_ACT_F (16 * 18 * 18)   // 5184
#define ENC_W_F   (16 * 9 * 28)    // 4032

__global__ __launch_bounds__(256) void k_encoder(const float* __restrict__ w_enc)
{
    __shared__ float act_s[ENC_ACT_F];   // [cl][yy][xx] pitch 18, 16 ch
    __shared__ float w_s[ENC_W_F];       // [cl][q][28]

    const int s = blockIdx.y >> 2;
    const int quarter = blockIdx.y & 3;
    const int b = blockIdx.z;
    const int tile = blockIdx.x;
    const int ty0 = (tile >> 2) * 16, tx0 = (tile & 3) * 16;
    const int tid = threadIdx.x;
    const int ci0 = quarter * 16;

    // w_s[(cl*9+q)*28 + k], zero for k>=25
    for (int i = tid; i < ENC_W_F; i += 256) {
        int k = i % 28, cq = i / 28;
        int cl = cq / 9, q = cq % 9;
        float v = 0.f;
        if (k < 25) v = w_enc[(k * 4 + s) * 576 + (ci0 + cl) * 9 + q];
        w_s[i] = v;
    }
    // act tile, pad=1, zero-fill
    for (int i = tid; i < ENC_ACT_F; i += 256) {
        int cl = i / 324, r = i % 324;
        int yy = r / 18, xx = r % 18;
        int gy = ty0 + yy - 1, gx = tx0 + xx - 1;
        float v = 0.f;
        if ((unsigned)gy < 64u && (unsigned)gx < 64u)
            v = g_act[((size_t)b * COMP_ + ci0 + cl) * P_ + gy * 64 + gx];
        act_s[i] = v;
    }
    __syncthreads();

    const int py = tid >> 4, px = tid & 15;
    ull acc2[13];
#pragma unroll
    for (int k = 0; k < 13; k++) acc2[k] = 0ull;

    for (int cl = 0; cl < 16; cl++) {
        float a[9];
        const float* ap = act_s + cl * 324 + py * 18 + px;
#pragma unroll
        for (int dy = 0; dy < 3; dy++)
#pragma unroll
            for (int dx = 0; dx < 3; dx++)
                a[dy * 3 + dx] = ap[dy * 18 + dx];

#pragma unroll
        for (int q = 0; q < 9; q++) {
            const ulonglong2* wq = (const ulonglong2*)(w_s + (cl * 9 + q) * 28);
            ull aa = pk2(a[q], a[q]);
            ulonglong2 w0 = wq[0], w1 = wq[1], w2 = wq[2];
            ulonglong2 w3 = wq[3], w4 = wq[4], w5 = wq[5];
            ull w6 = ((const ull*)(wq + 6))[0];
            acc2[0]  = fma2(w0.x, aa, acc2[0]);
            acc2[1]  = fma2(w0.y, aa, acc2[1]);
            acc2[2]  = fma2(w1.x, aa, acc2[2]);
            acc2[3]  = fma2(w1.y, aa, acc2[3]);
            acc2[4]  = fma2(w2.x, aa, acc2[4]);
            acc2[5]  = fma2(w2.y, aa, acc2[5]);
            acc2[6]  = fma2(w3.x, aa, acc2[6]);
            acc2[7]  = fma2(w3.y, aa, acc2[7]);
            acc2[8]  = fma2(w4.x, aa, acc2[8]);
            acc2[9]  = fma2(w4.y, aa, acc2[9]);
            acc2[10] = fma2(w5.x, aa, acc2[10]);
            acc2[11] = fma2(w5.y, aa, acc2[11]);
            acc2[12] = fma2(w6,   aa, acc2[12]);
        }
    }

    // store partial logits (no softmax) to g_part[quarter]
    const int gp = (ty0 + py) * 64 + tx0 + px;
    ull* mp = (ull*)(g_part[quarter] + (((size_t)b * S2_ + s) * P_ + gp) * MPAD_);
#pragma unroll
    for (int k = 0; k < 13; k++) mp[k] = acc2[k];
    ((float*)mp)[26] = 0.f; ((float*)mp)[27] = 0.f;
}

// ---------------------------------------------------------------------------
// Kernel 2.5: combine 4 partials + softmax(25) -> g_mask2.
// grid 256, block 256; each thread owns one mask row. Coalesced float4 via smem.
// ---------------------------------------------------------------------------
__global__ __launch_bounds__(256) void k_combine()
{
    __shared__ float sm[256 * MPAD_];
    const int tid = threadIdx.x;
    const size_t base = (size_t)blockIdx.x * 256 * MPAD_;   // float offset

    const float4* p0 = (const float4*)(g_part[0] + base);
    const float4* p1 = (const float4*)(g_part[1] + base);
    const float4* p2 = (const float4*)(g_part[2] + base);
    const float4* p3 = (const float4*)(g_part[3] + base);
    float4* smv = (float4*)sm;
#pragma unroll
    for (int j = 0; j < 7; j++) {
        int i = j * 256 + tid;
        float4 a = p0[i], b = p1[i], c = p2[i], d = p3[i];
        smv[i] = make_float4(a.x + b.x + c.x + d.x, a.y + b.y + c.y + d.y,
                             a.z + b.z + c.z + d.z, a.w + b.w + c.w + d.w);
    }
    __syncthreads();

    float v[25];
#pragma unroll
    for (int k = 0; k < 25; k++) v[k] = sm[tid * MPAD_ + k];
    float m = v[0];
#pragma unroll
    for (int k = 1; k < 25; k++) m = fmaxf(m, v[k]);
    float sum = 0.f;
#pragma unroll
    for (int k = 0; k < 25; k++) { v[k] = __expf(v[k] - m); sum += v[k]; }
    float inv = 1.f / sum;

    float4* mp = (float4*)(g_mask2 + base + (size_t)tid * MPAD_);
    mp[0] = make_float4(v[0]*inv,  v[1]*inv,  v[2]*inv,  v[3]*inv);
    mp[1] = make_float4(v[4]*inv,  v[5]*inv,  v[6]*inv,  v[7]*inv);
    mp[2] = make_float4(v[8]*inv,  v[9]*inv,  v[10]*inv, v[11]*inv);
    mp[3] = make_float4(v[12]*inv, v[13]*inv, v[14]*inv, v[15]*inv);
    mp[4] = make_float4(v[16]*inv, v[17]*inv, v[18]*inv, v[19]*inv);
    mp[5] = make_float4(v[20]*inv, v[21]*inv, v[22]*inv, v[23]*inv);
    mp[6] = make_float4(v[24]*inv, 0.f, 0.f, 0.f);
}

// ---------------------------------------------------------------------------
// Kernel 3: reassembly + pixel shuffle, FFMA2 s-pairs.  (R7 EXACT)
// grid (64 tiles of 8x8, 16 cgroups of 16, 4 b), block 256 = 64px * 4csub(4ch).
// ---------------------------------------------------------------------------
#define RA_XS_F  (16 * 480)                  // 7680
#define RA_MS_F  (64 * 108)                  // 6912
#define RA_SMEM_BYTES ((RA_XS_F + RA_MS_F) * 4)   // 58368

__global__ __launch_bounds__(256, 3) void k_reassemble(
    const float* __restrict__ x, float* __restrict__ out)
{
    extern __shared__ float rsm[];
    float* xs = rsm;                 // [cl][yy*40 + xx]
    float* ms = rsm + RA_XS_F;       // [px*108 + k*4 + s]

    const int b = blockIdx.z;
    const int cg = blockIdx.y;       // 16 channel groups of 16
    const int tile = blockIdx.x;
    const int ty0 = (tile >> 3) * 8, tx0 = (tile & 7) * 8;
    const int tid = threadIdx.x;

    for (int i = tid; i < 16 * 144; i += 256) {
        int cl = i / 144, r = i % 144;
        int yy = r / 12, xx = r % 12;
        int gy = ty0 + yy - 2, gx = tx0 + xx - 2;
        float v = 0.f;
        if ((unsigned)gy < 64u && (unsigned)gx < 64u)
            v = x[(((size_t)b * C_ + cg * 16 + cl) * 64 + gy) * 64 + gx];
        xs[cl * 480 + yy * 40 + xx] = v;
    }
    for (int i = tid; i < 64 * 4 * 7; i += 256) {
        int px = i / 28, rem = i % 28;
        int s = rem / 7, j = rem % 7;
        int gp = (ty0 + (px >> 3)) * 64 + tx0 + (px & 7);
        float4 v = *((const float4*)(g_mask2 +
                     (((size_t)b * S2_ + s) * P_ + gp) * MPAD_) + j);
        float* dst = ms + px * 108 + s;
        int k = j * 4;
        dst[(k + 0) * 4] = v.x;
        if (k + 1 < 25) dst[(k + 1) * 4] = v.y;
        if (k + 2 < 25) dst[(k + 2) * 4] = v.z;
        if (k + 3 < 25) dst[(k + 3) * 4] = v.w;
    }
    __syncthreads();

    const int csub = tid >> 6;
    const int px   = tid & 63;
    const int py = px >> 3, pxl = px & 7;

    ull acc01[4], acc23[4];
#pragma unroll
    for (int ch = 0; ch < 4; ch++) { acc01[ch] = 0ull; acc23[ch] = 0ull; }

    const float* xbase = xs + csub * 4 * 480 + py * 40 + pxl;
    const ulonglong2* mrow = (const ulonglong2*)(ms + px * 108);

#pragma unroll
    for (int chunk = 0; chunk < 3; chunk++) {
        const int kb = chunk * 10;
        const int nk = (chunk == 2) ? 5 : 10;

        ull mk01[10], mk23[10];
#pragma unroll
        for (int j = 0; j < 10; j++) {
            if (j < nk) {
                ulonglong2 m = mrow[kb + j];
                mk01[j] = m.x; mk23[j] = m.y;
            }
        }

#pragma unroll
        for (int ch = 0; ch < 4; ch++) {
            const float* xp = xbase + ch * 480;
#pragma unroll
            for (int j = 0; j < 10; j++) {
                if (j < nk) {
                    int k = kb + j;
                    float xv = xp[(k / 5) * 40 + (k % 5)];
                    ull xx = pk2(xv, xv);
                    acc01[ch] = fma2(mk01[j], xx, acc01[ch]);
                    acc23[ch] = fma2(mk23[j], xx, acc23[ch]);
                }
            }
        }
    }

    const int gy = ty0 + py, gx = tx0 + pxl;
    size_t base = (((size_t)b * C_ + cg * 16 + csub * 4) * 128 + 2 * gy) * 128 + 2 * gx;
#pragma unroll
    for (int ch = 0; ch < 4; ch++) {
        *(ull*)(out + base)       = acc01[ch];
        *(ull*)(out + base + 128) = acc23[ch];
        base += (size_t)128 * 128;
    }
}

// ---------------------------------------------------------------------------
extern "C" void kernel_launch(void* const* d_in, const int* in_sizes, int n_in,
                              void* d_out, int out_size)
{
    const float* x       = (const float*)d_in[0];
    const float* w_comp  = (const float*)d_in[1];
    const float* bn_g    = (const float*)d_in[2];
    const float* bn_b    = (const float*)d_in[3];
    const float* bn_m    = (const float*)d_in[4];
    const float* bn_v    = (const float*)d_in[5];
    const float* w_enc   = (const float*)d_in[6];
    float* out = (float*)d_out;

    cudaFuncSetAttribute(k_reassemble, cudaFuncAttributeMaxDynamicSharedMemorySize,
                         RA_SMEM_BYTES);

    dim3 g1(16, 8, B_);
    k_compress<<<g1, 512>>>(x, w_comp, bn_g, bn_b, bn_m, bn_v);

    dim3 g2(16, 16, B_);
    k_encoder<<<g2, 256>>>(w_enc);

    k_combine<<<256, 256>>>();

    dim3 g3(64, 16, B_);
    k_reassemble<<<g3, 256, RA_SMEM_BYTES>>>(x, out);
}